// round 14
// baseline (speedup 1.0000x reference)
#include <cuda_runtime.h>
#include <cuda_bf16.h>
#include <math.h>

#define HWn   65536
#define Wimg  256
#define Himg  256
#define DIM   64
#define CH6   384
#define CH2   128
#define HID   192
#define EPS   1e-5f
#define STRK  72      // padded k-major stride for mma A-operand staging

typedef unsigned int u32;
typedef __nv_bfloat16  bf16;
typedef __nv_bfloat162 bf162;

// ---------------------------------------------------------------------------
// Scratch (device globals; no runtime allocation)
// ---------------------------------------------------------------------------
__device__ bf16  g_h [(size_t)2 * CH6 * HWn];   // pconv output (bf16 storage)
__device__ bf16  g_h2[(size_t)2 * CH6 * HWn];   // dwconv output (bf16 storage)
__device__ float g_x1[(size_t)2 * DIM * HWn];   // residual carrier (fp32)
__device__ float g_gker[CH6 * 64];
__device__ int   g_isdelta[CH6];

// fragment-packed tf32 weights
__device__ uint4 g_pkA0[24 * 8 * 32];   // attn pin  [384x64] A-frags
__device__ uint4 g_pkA1[24 * 8 * 32];   // ffn  pin  [384x64] A-frags
__device__ uint2 g_pkB2[16 * 8 * 32];   // attn pout [64x128] B-frags
__device__ uint2 g_pkB3[24 * 8 * 32];   // ffn  pout [64x192] B-frags

__device__ __forceinline__ u32 to_tf32(float f) {
    u32 r; asm("cvt.rna.tf32.f32 %0, %1;" : "=r"(r) : "f"(f)); return r;
}
__device__ __forceinline__ void mma_tf32(float d[4], u32 a0, u32 a1, u32 a2, u32 a3,
                                         u32 b0, u32 b1) {
    asm volatile(
        "mma.sync.aligned.m16n8k8.row.col.f32.tf32.tf32.f32 "
        "{%0,%1,%2,%3}, {%4,%5,%6,%7}, {%8,%9}, {%0,%1,%2,%3};"
        : "+f"(d[0]), "+f"(d[1]), "+f"(d[2]), "+f"(d[3])
        : "r"(a0), "r"(a1), "r"(a2), "r"(a3), "r"(b0), "r"(b1));
}
__device__ __forceinline__ void bf8_to_f8(const uint4 v, float* f) {
    float2 t;
    t = __bfloat1622float2(*(const bf162*)&v.x); f[0] = t.x; f[1] = t.y;
    t = __bfloat1622float2(*(const bf162*)&v.y); f[2] = t.x; f[3] = t.y;
    t = __bfloat1622float2(*(const bf162*)&v.z); f[4] = t.x; f[5] = t.y;
    t = __bfloat1622float2(*(const bf162*)&v.w); f[6] = t.x; f[7] = t.y;
}
__device__ __forceinline__ float tanh_ap(float y) {
    float r; asm("tanh.approx.f32 %0, %1;" : "=f"(r) : "f"(y)); return r;
}

// ---------------------------------------------------------------------------
// K0: ONE merged preparation launch (spectral kernels + all weight packing)
// ---------------------------------------------------------------------------
__global__ void k_prep_all(const float* __restrict__ fp,
                           const float* __restrict__ apin,
                           const float* __restrict__ fpin,
                           const float* __restrict__ apout,
                           const float* __restrict__ fpout)
{
    int blk = blockIdx.x;
    int tid = threadIdx.x;

    if (blk < 384) {
        int c = blk, t = tid;
        int x = t >> 3, y = t & 7;
        float s = 0.f;
        #pragma unroll
        for (int kx = 0; kx < 8; kx++) {
            #pragma unroll
            for (int ky = 0; ky < 8; ky++) {
                float Sv = (ky <= 4) ? fp[c * 40 + kx * 5 + ky]
                                     : fp[c * 40 + (((8 - kx) & 7) * 5) + (8 - ky)];
                int m = (kx * x + ky * y) & 7;
                s += Sv * cospif((float)m * 0.25f);
            }
        }
        s *= (1.f / 64.f);
        g_gker[c * 64 + t] = s;
        float target = (t == 0) ? 1.f : 0.f;
        int ok = __syncthreads_and(fabsf(s - target) <= 1e-5f);
        if (t == 0) g_isdelta[c] = ok;
        return;
    }

    int lane = tid & 31;
    int g = lane >> 2, q4 = lane & 3;

    if (blk < 576) {
        int which = (blk >= 480);
        const float* W = which ? fpin : apin;
        int combo = (blk - (which ? 480 : 384)) * 2 + (tid >> 5);
        int s = combo >> 3, ks = combo & 7;
        int m0 = s * 16, k0 = ks * 8;
        uint4 v;
        v.x = to_tf32(W[(m0 + g) * 64 + k0 + q4]);
        v.y = to_tf32(W[(m0 + g + 8) * 64 + k0 + q4]);
        v.z = to_tf32(W[(m0 + g) * 64 + k0 + q4 + 4]);
        v.w = to_tf32(W[(m0 + g + 8) * 64 + k0 + q4 + 4]);
        (which ? g_pkA1 : g_pkA0)[combo * 32 + lane] = v;
        return;
    }

    int which = (blk >= 640);
    const float* W = which ? fpout : apout;
    int IC = which ? HID : CH2;
    int combo = (blk - (which ? 640 : 576)) * 2 + (tid >> 5);
    int ks = combo >> 3, nt = combo & 7;
    int n = nt * 8, k0 = ks * 8;
    uint2 v;
    v.x = to_tf32(W[(n + g) * IC + k0 + q4]);
    v.y = to_tf32(W[(n + g) * IC + k0 + q4 + 4]);
    (which ? g_pkB3 : g_pkB2)[combo * 32 + lane] = v;
}

// ---------------------------------------------------------------------------
// K1/K4: fused LayerNorm + 1x1 conv [384oc x 64ic] via tf32 mma -> bf16 g_h
// grid 2048 (b*1024+chunk), 256 threads; smem s_in [64][72] (18.4KB)
// ---------------------------------------------------------------------------
__global__ void __launch_bounds__(256, 3)
k_ln_pconv(const float* __restrict__ xin,
           const float* __restrict__ nw,
           const float* __restrict__ nb,
           int which)       // 0: attn (in=xin, pkA0)  1: ffn (in=g_x1, pkA1)
{
    __shared__ u32 s_in[64 * STRK];

    const float* in = which ? g_x1 : xin;
    const uint4* pk = which ? g_pkA1 : g_pkA0;

    int tid = threadIdx.x;
    int b   = blockIdx.x >> 10;
    int ch  = blockIdx.x & 1023;
    size_t pxoff = (size_t)ch * 64;

    int warp = tid >> 5, lane = tid & 31;

    // LayerNorm: 8 warps x 8 rows
    #pragma unroll
    for (int r = 0; r < 8; r++) {
        int ic = warp * 8 + r;
        const float* xr = in + ((size_t)(b * DIM + ic)) * HWn + pxoff;
        float2 v = *(const float2*)&xr[lane * 2];
        float s = v.x + v.y;
        float q = v.x * v.x + v.y * v.y;
        #pragma unroll
        for (int o = 16; o; o >>= 1) {
            s += __shfl_xor_sync(0xffffffffu, s, o);
            q += __shfl_xor_sync(0xffffffffu, q, o);
        }
        float mu  = s * (1.f / 64.f);
        float var = q * (1.f / 64.f) - mu * mu;
        float inv = rsqrtf(var + EPS);
        int j = lane * 2;
        float y0 = (v.x - mu) * inv * nw[j]     + nb[j];
        float y1 = (v.y - mu) * inv * nw[j + 1] + nb[j + 1];
        uint2 pkv = make_uint2(to_tf32(y0), to_tf32(y1));
        *(uint2*)&s_in[ic * STRK + j] = pkv;
    }
    __syncthreads();

    int g  = lane >> 2;
    int q4 = lane & 3;

    for (int s = warp; s < 24; s += 8) {
        int m0 = s * 16;
        float d[8][4];
        #pragma unroll
        for (int nt = 0; nt < 8; nt++)
            #pragma unroll
            for (int e = 0; e < 4; e++) d[nt][e] = 0.f;

        #pragma unroll
        for (int ks = 0; ks < 8; ks++) {
            uint4 af = pk[(s * 8 + ks) * 32 + lane];
            int k0 = ks * 8;
            #pragma unroll
            for (int nt = 0; nt < 8; nt++) {
                int n = nt * 8;
                u32 b0 = s_in[(k0 + q4) * STRK + n + g];
                u32 b1 = s_in[(k0 + q4 + 4) * STRK + n + g];
                mma_tf32(d[nt], af.x, af.y, af.z, af.w, b0, b1);
            }
        }
        #pragma unroll
        for (int nt = 0; nt < 8; nt++) {
            int px = nt * 8 + q4 * 2;
            *(bf162*)&g_h[((size_t)(b * CH6 + m0 + g)) * HWn + pxoff + px] =
                __floats2bfloat162_rn(d[nt][0], d[nt][1]);
            *(bf162*)&g_h[((size_t)(b * CH6 + m0 + g + 8)) * HWn + pxoff + px] =
                __floats2bfloat162_rn(d[nt][2], d[nt][3]);
        }
    }
}

// ---------------------------------------------------------------------------
// K4b: generic FFN spectral conv, in-place on g_h (per-channel delta skip)
// ---------------------------------------------------------------------------
__global__ void __launch_bounds__(256)
k_spectral()
{
    int b  = blockIdx.x >> 10;
    int ch = blockIdx.x & 1023;
    for (int c = threadIdx.x; c < CH6; c += 256) {
        if (g_isdelta[c]) continue;
        bf16* p = g_h + ((size_t)(b * CH6 + c)) * HWn + (size_t)ch * 64;
        float t[64];
        #pragma unroll
        for (int i = 0; i < 64; i++) t[i] = __bfloat162float(p[i]);
        const float* gk = &g_gker[c * 64];
        float o[64];
        for (int i = 0; i < 8; i++)
            for (int j = 0; j < 8; j++) {
                float v = 0.f;
                for (int a = 0; a < 8; a++) {
                    int ri = ((i - a) & 7) * 8;
                    #pragma unroll
                    for (int bb = 0; bb < 8; bb++)
                        v += t[ri + ((j - bb) & 7)] * gk[a * 8 + bb];
                }
                o[i * 8 + j] = v;
            }
        #pragma unroll
        for (int i = 0; i < 64; i++) p[i] = __float2bfloat16(o[i]);
    }
}

// ---------------------------------------------------------------------------
// K2/K5: depthwise 3x3 (bf16 in/out)
// ---------------------------------------------------------------------------
__global__ void __launch_bounds__(256, 4)
k_dw(const float* __restrict__ wt)
{
    __shared__ float s[34][Wimg];
    int plane = blockIdx.y;
    int c = plane % CH6;
    int r0 = blockIdx.x * 32;
    int tid = threadIdx.x;
    const bf16* ip = g_h  + (size_t)plane * HWn;
    bf16*       op = g_h2 + (size_t)plane * HWn;

    // staged load: 34 rows x 32 uint4-slots = 1088 slots
    #pragma unroll
    for (int it = 0; it < 5; it++) {
        int pid = tid + it * 256;
        if (pid < 1088) {
            int row = pid >> 5;            // 0..33
            int q8  = (pid & 31) * 8;      // 0..248
            int gr = r0 + row - 1;
            if (gr >= 0 && gr < Himg) {
                uint4 v = *(const uint4*)&ip[gr * Wimg + q8];
                float f[8];
                bf8_to_f8(v, f);
                *(float4*)&s[row][q8]     = *(float4*)&f[0];
                *(float4*)&s[row][q8 + 4] = *(float4*)&f[4];
            } else {
                float4 z = make_float4(0.f, 0.f, 0.f, 0.f);
                *(float4*)&s[row][q8]     = z;
                *(float4*)&s[row][q8 + 4] = z;
            }
        }
    }
    float w[9];
    #pragma unroll
    for (int i = 0; i < 9; i++) w[i] = __ldg(&wt[c * 9 + i]);
    __syncthreads();

    int rgrp = tid >> 6;                // 0..3
    int c0 = (tid & 63) * 4;            // 0,4,...,252
    int srow0 = rgrp * 8;

    float p0[4] = {0.f, 0.f, 0.f, 0.f};
    float p1[4] = {0.f, 0.f, 0.f, 0.f};
    #pragma unroll
    for (int rr = 0; rr < 10; rr++) {
        int sr = srow0 + rr;
        float4 m = *(const float4*)&s[sr][c0];
        float mm[6];
        mm[0] = (c0 > 0)          ? s[sr][c0 - 1] : 0.f;
        mm[1] = m.x; mm[2] = m.y; mm[3] = m.z; mm[4] = m.w;
        mm[5] = (c0 + 4 < Wimg)   ? s[sr][c0 + 4] : 0.f;

        float h0[4], h1[4], h2[4];
        #pragma unroll
        for (int j = 0; j < 4; j++) {
            h0[j] = fmaf(mm[j], w[0], fmaf(mm[j + 1], w[1], mm[j + 2] * w[2]));
            h1[j] = fmaf(mm[j], w[3], fmaf(mm[j + 1], w[4], mm[j + 2] * w[5]));
            h2[j] = fmaf(mm[j], w[6], fmaf(mm[j + 1], w[7], mm[j + 2] * w[8]));
        }
        if (rr >= 2) {
            int orow = r0 + srow0 + rr - 2;
            uint2 st;
            *(bf162*)&st.x = __floats2bfloat162_rn(p1[0] + h2[0], p1[1] + h2[1]);
            *(bf162*)&st.y = __floats2bfloat162_rn(p1[2] + h2[2], p1[3] + h2[3]);
            *(uint2*)&op[orow * Wimg + c0] = st;
        }
        #pragma unroll
        for (int j = 0; j < 4; j++) {
            p1[j] = p0[j] + h1[j];
            p0[j] = h0[j];
        }
    }
}

// ---------------------------------------------------------------------------
// K3: attention tail: t = v * circconv8x8(q,k); x1 = x + W2 @ t
// grid 2048, 256 threads; dynamic smem 64KB
// q/k smem: half-row (16B) granularity XOR swizzle:
//   addr_u32(c, rr, t) = c*64 + (((2*rr + t) ^ (c&7)) << 2)
// conv threads: c = tid&127, h = tid>>7  -> quarter-warps span 8 channels
// => every conv LDS.128 is perfectly bank-tiled (1 phase / quarter-warp)
// ---------------------------------------------------------------------------
__global__ void __launch_bounds__(256, 3)
k_attn(const float* __restrict__ x)
{
    extern __shared__ float sh[];
    float* s_q = sh;                    // [128][64], half-row swizzled
    float* s_k = sh + 8192;             // [128][64], half-row swizzled
    u32*   s_t_u = (u32*)sh;            // [128][STRK] tf32, overlays q (+k head)

    int tid = threadIdx.x;
    int b   = blockIdx.x >> 10;
    int ch  = blockIdx.x & 1023;
    size_t base = (size_t)b * CH6 * HWn + (size_t)ch * 64;

    // stage q,k: uint4 loads (8 bf16 = one row = two swizzled half-rows)
    #pragma unroll
    for (int it = 0; it < 4; it++) {
        int i = tid + it * 256;
        int c = i >> 3, r = i & 7;
        int sw = c & 7;
        int a0 = c * 64 + (((2 * r + 0) ^ sw) << 2);
        int a1 = c * 64 + (((2 * r + 1) ^ sw) << 2);
        uint4 qv = *(const uint4*)&g_h2[base + (size_t)c * HWn + r * 8];
        uint4 kv = *(const uint4*)&g_h2[base + (size_t)(CH2 + c) * HWn + r * 8];
        float qf[8], kf[8];
        bf8_to_f8(qv, qf);
        bf8_to_f8(kv, kf);
        *(float4*)&s_q[a0] = *(float4*)&qf[0];
        *(float4*)&s_q[a1] = *(float4*)&qf[4];
        *(float4*)&s_k[a0] = *(float4*)&kf[0];
        *(float4*)&s_k[a1] = *(float4*)&kf[4];
    }
    __syncthreads();

    // circular conv: thread = (channel c=tid&127, half h=tid>>7); rows i0..i0+3
    int c  = tid & 127;
    int i0 = (tid >> 7) * 4;
    int sw = (c & 7);
    float o[4][8];
    #pragma unroll
    for (int di = 0; di < 4; di++)
        #pragma unroll
        for (int j = 0; j < 8; j++) o[di][j] = 0.f;
    {
        const float* qb = &s_q[c * 64];
        const float* kb = &s_k[c * 64];
        #pragma unroll 2
        for (int a = 0; a < 8; a++) {
            float kv[8];
            *(float4*)&kv[0] = *(const float4*)&kb[((2 * a + 0) ^ sw) << 2];
            *(float4*)&kv[4] = *(const float4*)&kb[((2 * a + 1) ^ sw) << 2];
            #pragma unroll
            for (int di = 0; di < 4; di++) {
                int rr = (i0 + di - a) & 7;
                float qv[8];
                *(float4*)&qv[0] = *(const float4*)&qb[((2 * rr + 0) ^ sw) << 2];
                *(float4*)&qv[4] = *(const float4*)&qb[((2 * rr + 1) ^ sw) << 2];
                #pragma unroll
                for (int bb = 0; bb < 8; bb++) {
                    float kvv = kv[bb];
                    #pragma unroll
                    for (int j = 0; j < 8; j++)
                        o[di][j] += qv[(j - bb) & 7] * kvv;
                }
            }
        }
    }
    {
        const bf16* vbase = g_h2 + base + (size_t)(2 * CH2 + c) * HWn;
        #pragma unroll
        for (int di = 0; di < 4; di++) {
            uint4 vv = *(const uint4*)&vbase[(i0 + di) * 8];
            float vf[8];
            bf8_to_f8(vv, vf);
            #pragma unroll
            for (int j = 0; j < 8; j++) o[di][j] *= vf[j];
        }
    }
    __syncthreads();     // all conv reads of q/k done; safe to overlay t
    #pragma unroll
    for (int di = 0; di < 4; di++) {
        uint4 p0 = make_uint4(to_tf32(o[di][0]), to_tf32(o[di][1]),
                              to_tf32(o[di][2]), to_tf32(o[di][3]));
        uint4 p1 = make_uint4(to_tf32(o[di][4]), to_tf32(o[di][5]),
                              to_tf32(o[di][6]), to_tf32(o[di][7]));
        *(uint4*)&s_t_u[c * STRK + (i0 + di) * 8]     = p0;
        *(uint4*)&s_t_u[c * STRK + (i0 + di) * 8 + 4] = p1;
    }
    __syncthreads();

    // mma: M=64px, N=64oc, K=128
    int warp = tid >> 5, lane = tid & 31;
    int g = lane >> 2, q4 = lane & 3;
    int m0 = (warp & 3) * 16, n0 = (warp >> 2) * 32;
    int ntg0 = (warp >> 2) * 4;

    float d[4][4];
    #pragma unroll
    for (int nt = 0; nt < 4; nt++)
        #pragma unroll
        for (int e = 0; e < 4; e++) d[nt][e] = 0.f;

    #pragma unroll 4
    for (int ks = 0; ks < 16; ks++) {
        int k0 = ks * 8;
        u32 a0 = s_t_u[(k0 + q4) * STRK + m0 + g];
        u32 a1 = s_t_u[(k0 + q4) * STRK + m0 + g + 8];
        u32 a2 = s_t_u[(k0 + q4 + 4) * STRK + m0 + g];
        u32 a3 = s_t_u[(k0 + q4 + 4) * STRK + m0 + g + 8];
        #pragma unroll
        for (int nt = 0; nt < 4; nt++) {
            uint2 bf = g_pkB2[(ks * 8 + ntg0 + nt) * 32 + lane];
            mma_tf32(d[nt], a0, a1, a2, a3, bf.x, bf.y);
        }
    }

    #pragma unroll
    for (int nt = 0; nt < 4; nt++) {
        int oc = n0 + nt * 8 + q4 * 2;
        int px = m0 + g;
        size_t a00 = ((size_t)(b * DIM + oc)) * HWn + (size_t)ch * 64;
        size_t a01 = a00 + HWn;
        g_x1[a00 + px]     = x[a00 + px]     + d[nt][0];
        g_x1[a01 + px]     = x[a01 + px]     + d[nt][1];
        g_x1[a00 + px + 8] = x[a00 + px + 8] + d[nt][2];
        g_x1[a01 + px + 8] = x[a01 + px + 8] + d[nt][3];
    }
}

// ---------------------------------------------------------------------------
// K6: FFN tail: t = gelu(h2a)*h2b; out = x1 + W3 @ t   (tanh.approx gelu)
// ---------------------------------------------------------------------------
__global__ void __launch_bounds__(256, 3)
k_ffn_out(float* __restrict__ dout)
{
    extern __shared__ float sh[];
    u32* s_t_u = (u32*)sh;              // [192][STRK]

    int tid = threadIdx.x;
    int b   = blockIdx.x >> 10;
    int ch  = blockIdx.x & 1023;
    size_t base = (size_t)b * CH6 * HWn + (size_t)ch * 64;

    #pragma unroll
    for (int it = 0; it < 6; it++) {
        int i = tid + it * 256;
        int c = i >> 3, p8 = (i & 7) * 8;
        uint4 av4 = *(const uint4*)&g_h2[base + (size_t)c * HWn + p8];
        uint4 bv4 = *(const uint4*)&g_h2[base + (size_t)(HID + c) * HWn + p8];
        float af[8], bfv[8];
        bf8_to_f8(av4, af);
        bf8_to_f8(bv4, bfv);
        u32 tv[8];
        #pragma unroll
        for (int j = 0; j < 8; j++) {
            float a = af[j];
            float y = 0.7978845608028654f * (a + 0.044715f * a * a * a);
            float ge = 0.5f * a * (1.f + tanh_ap(y));
            tv[j] = to_tf32(ge * bfv[j]);
        }
        *(uint4*)&s_t_u[c * STRK + p8]     = *(uint4*)&tv[0];
        *(uint4*)&s_t_u[c * STRK + p8 + 4] = *(uint4*)&tv[4];
    }
    __syncthreads();

    int warp = tid >> 5, lane = tid & 31;
    int g = lane >> 2, q4 = lane & 3;
    int m0 = (warp & 3) * 16, n0 = (warp >> 2) * 32;
    int ntg0 = (warp >> 2) * 4;

    float d[4][4];
    #pragma unroll
    for (int nt = 0; nt < 4; nt++)
        #pragma unroll
        for (int e = 0; e < 4; e++) d[nt][e] = 0.f;

    #pragma unroll 4
    for (int ks = 0; ks < 24; ks++) {
        int k0 = ks * 8;
        u32 a0 = s_t_u[(k0 + q4) * STRK + m0 + g];
        u32 a1 = s_t_u[(k0 + q4) * STRK + m0 + g + 8];
        u32 a2 = s_t_u[(k0 + q4 + 4) * STRK + m0 + g];
        u32 a3 = s_t_u[(k0 + q4 + 4) * STRK + m0 + g + 8];
        #pragma unroll
        for (int nt = 0; nt < 4; nt++) {
            uint2 bf = g_pkB3[(ks * 8 + ntg0 + nt) * 32 + lane];
            mma_tf32(d[nt], a0, a1, a2, a3, bf.x, bf.y);
        }
    }

    #pragma unroll
    for (int nt = 0; nt < 4; nt++) {
        int oc = n0 + nt * 8 + q4 * 2;
        int px = m0 + g;
        size_t a00 = ((size_t)(b * DIM + oc)) * HWn + (size_t)ch * 64;
        size_t a01 = a00 + HWn;
        dout[a00 + px]     = g_x1[a00 + px]     + d[nt][0];
        dout[a01 + px]     = g_x1[a01 + px]     + d[nt][1];
        dout[a00 + px + 8] = g_x1[a00 + px + 8] + d[nt][2];
        dout[a01 + px + 8] = g_x1[a01 + px + 8] + d[nt][3];
    }
}

// ---------------------------------------------------------------------------
// launcher
// ---------------------------------------------------------------------------
extern "C" void kernel_launch(void* const* d_in, const int* in_sizes, int n_in,
                              void* d_out, int out_size)
{
    const float* x     = (const float*)d_in[0];
    const float* n1w   = (const float*)d_in[1];
    const float* n1b   = (const float*)d_in[2];
    const float* apin  = (const float*)d_in[3];
    const float* adw   = (const float*)d_in[4];
    const float* apout = (const float*)d_in[5];
    const float* n2w   = (const float*)d_in[6];
    const float* n2b   = (const float*)d_in[7];
    const float* fpin  = (const float*)d_in[8];
    const float* fdw   = (const float*)d_in[9];
    const float* ffft  = (const float*)d_in[10];
    const float* fpout = (const float*)d_in[11];
    float* out         = (float*)d_out;

    (void)in_sizes; (void)n_in; (void)out_size;

    cudaFuncSetAttribute(k_attn,    cudaFuncAttributeMaxDynamicSharedMemorySize, 65536);
    cudaFuncSetAttribute(k_ffn_out, cudaFuncAttributeMaxDynamicSharedMemorySize, 55296);

    // single merged preparation launch
    k_prep_all<<<736, 64>>>(ffft, apin, fpin, apout, fpout);

    // attention branch
    k_ln_pconv<<<2048, 256>>>(x, n1w, n1b, 0);
    k_dw<<<dim3(8, 2 * CH6), 256>>>(adw);
    k_attn<<<2048, 256, 65536>>>(x);

    // FFN branch
    k_ln_pconv<<<2048, 256>>>(x, n2w, n2b, 1);
    k_spectral<<<2048, 256>>>();
    k_dw<<<dim3(8, 2 * CH6), 256>>>(fdw);
    k_ffn_out<<<2048, 256, 55296>>>(out);
}

// round 15
// speedup vs baseline: 1.0714x; 1.0714x over previous
#include <cuda_runtime.h>
#include <cuda_bf16.h>
#include <math.h>

#define HWn   65536
#define Wimg  256
#define Himg  256
#define DIM   64
#define CH6   384
#define CH2   128
#define HID   192
#define EPS   1e-5f
#define STRK  72      // padded k-major stride for mma A-operand staging

typedef unsigned int u32;
typedef __nv_bfloat16  bf16;
typedef __nv_bfloat162 bf162;

// ---------------------------------------------------------------------------
// Scratch (device globals; no runtime allocation)
// ---------------------------------------------------------------------------
__device__ bf16  g_h [(size_t)2 * CH6 * HWn];   // pconv output (bf16 storage)
__device__ bf16  g_h2[(size_t)2 * CH6 * HWn];   // dwconv output (bf16 storage)
__device__ float g_x1[(size_t)2 * DIM * HWn];   // residual carrier (fp32)
__device__ float g_gker[CH6 * 64];
__device__ int   g_isdelta[CH6];

// fragment-packed tf32 weights
__device__ uint4 g_pkA0[24 * 8 * 32];   // attn pin  [384x64] A-frags
__device__ uint4 g_pkA1[24 * 8 * 32];   // ffn  pin  [384x64] A-frags
__device__ uint2 g_pkB2[16 * 8 * 32];   // attn pout [64x128] B-frags
__device__ uint2 g_pkB3[24 * 8 * 32];   // ffn  pout [64x192] B-frags

__device__ __forceinline__ u32 to_tf32(float f) {
    u32 r; asm("cvt.rna.tf32.f32 %0, %1;" : "=r"(r) : "f"(f)); return r;
}
__device__ __forceinline__ void mma_tf32(float d[4], u32 a0, u32 a1, u32 a2, u32 a3,
                                         u32 b0, u32 b1) {
    asm volatile(
        "mma.sync.aligned.m16n8k8.row.col.f32.tf32.tf32.f32 "
        "{%0,%1,%2,%3}, {%4,%5,%6,%7}, {%8,%9}, {%0,%1,%2,%3};"
        : "+f"(d[0]), "+f"(d[1]), "+f"(d[2]), "+f"(d[3])
        : "r"(a0), "r"(a1), "r"(a2), "r"(a3), "r"(b0), "r"(b1));
}
__device__ __forceinline__ void bf8_to_f8(const uint4 v, float* f) {
    float2 t;
    t = __bfloat1622float2(*(const bf162*)&v.x); f[0] = t.x; f[1] = t.y;
    t = __bfloat1622float2(*(const bf162*)&v.y); f[2] = t.x; f[3] = t.y;
    t = __bfloat1622float2(*(const bf162*)&v.z); f[4] = t.x; f[5] = t.y;
    t = __bfloat1622float2(*(const bf162*)&v.w); f[6] = t.x; f[7] = t.y;
}
__device__ __forceinline__ float tanh_ap(float y) {
    float r; asm("tanh.approx.f32 %0, %1;" : "=f"(r) : "f"(y)); return r;
}

// ---------------------------------------------------------------------------
// K0: ONE merged preparation launch (spectral kernels + all weight packing)
// ---------------------------------------------------------------------------
__global__ void k_prep_all(const float* __restrict__ fp,
                           const float* __restrict__ apin,
                           const float* __restrict__ fpin,
                           const float* __restrict__ apout,
                           const float* __restrict__ fpout)
{
    int blk = blockIdx.x;
    int tid = threadIdx.x;

    if (blk < 384) {
        int c = blk, t = tid;
        int x = t >> 3, y = t & 7;
        float s = 0.f;
        #pragma unroll
        for (int kx = 0; kx < 8; kx++) {
            #pragma unroll
            for (int ky = 0; ky < 8; ky++) {
                float Sv = (ky <= 4) ? fp[c * 40 + kx * 5 + ky]
                                     : fp[c * 40 + (((8 - kx) & 7) * 5) + (8 - ky)];
                int m = (kx * x + ky * y) & 7;
                s += Sv * cospif((float)m * 0.25f);
            }
        }
        s *= (1.f / 64.f);
        g_gker[c * 64 + t] = s;
        float target = (t == 0) ? 1.f : 0.f;
        int ok = __syncthreads_and(fabsf(s - target) <= 1e-5f);
        if (t == 0) g_isdelta[c] = ok;
        return;
    }

    int lane = tid & 31;
    int g = lane >> 2, q4 = lane & 3;

    if (blk < 576) {
        int which = (blk >= 480);
        const float* W = which ? fpin : apin;
        int combo = (blk - (which ? 480 : 384)) * 2 + (tid >> 5);
        int s = combo >> 3, ks = combo & 7;
        int m0 = s * 16, k0 = ks * 8;
        uint4 v;
        v.x = to_tf32(W[(m0 + g) * 64 + k0 + q4]);
        v.y = to_tf32(W[(m0 + g + 8) * 64 + k0 + q4]);
        v.z = to_tf32(W[(m0 + g) * 64 + k0 + q4 + 4]);
        v.w = to_tf32(W[(m0 + g + 8) * 64 + k0 + q4 + 4]);
        (which ? g_pkA1 : g_pkA0)[combo * 32 + lane] = v;
        return;
    }

    int which = (blk >= 640);
    const float* W = which ? fpout : apout;
    int IC = which ? HID : CH2;
    int combo = (blk - (which ? 640 : 576)) * 2 + (tid >> 5);
    int ks = combo >> 3, nt = combo & 7;
    int n = nt * 8, k0 = ks * 8;
    uint2 v;
    v.x = to_tf32(W[(n + g) * IC + k0 + q4]);
    v.y = to_tf32(W[(n + g) * IC + k0 + q4 + 4]);
    (which ? g_pkB3 : g_pkB2)[combo * 32 + lane] = v;
}

// ---------------------------------------------------------------------------
// K1/K4: fused LayerNorm + 1x1 conv [384oc x 64ic] via tf32 mma -> bf16 g_h
// ---------------------------------------------------------------------------
__global__ void __launch_bounds__(256, 3)
k_ln_pconv(const float* __restrict__ xin,
           const float* __restrict__ nw,
           const float* __restrict__ nb,
           int which)       // 0: attn (in=xin, pkA0)  1: ffn (in=g_x1, pkA1)
{
    __shared__ u32 s_in[64 * STRK];

    const float* in = which ? g_x1 : xin;
    const uint4* pk = which ? g_pkA1 : g_pkA0;

    int tid = threadIdx.x;
    int b   = blockIdx.x >> 10;
    int ch  = blockIdx.x & 1023;
    size_t pxoff = (size_t)ch * 64;

    int warp = tid >> 5, lane = tid & 31;

    // LayerNorm: 8 warps x 8 rows
    #pragma unroll
    for (int r = 0; r < 8; r++) {
        int ic = warp * 8 + r;
        const float* xr = in + ((size_t)(b * DIM + ic)) * HWn + pxoff;
        float2 v = *(const float2*)&xr[lane * 2];
        float s = v.x + v.y;
        float q = v.x * v.x + v.y * v.y;
        #pragma unroll
        for (int o = 16; o; o >>= 1) {
            s += __shfl_xor_sync(0xffffffffu, s, o);
            q += __shfl_xor_sync(0xffffffffu, q, o);
        }
        float mu  = s * (1.f / 64.f);
        float var = q * (1.f / 64.f) - mu * mu;
        float inv = rsqrtf(var + EPS);
        int j = lane * 2;
        float y0 = (v.x - mu) * inv * nw[j]     + nb[j];
        float y1 = (v.y - mu) * inv * nw[j + 1] + nb[j + 1];
        uint2 pkv = make_uint2(to_tf32(y0), to_tf32(y1));
        *(uint2*)&s_in[ic * STRK + j] = pkv;
    }
    __syncthreads();

    int g  = lane >> 2;
    int q4 = lane & 3;

    for (int s = warp; s < 24; s += 8) {
        int m0 = s * 16;
        float d[8][4];
        #pragma unroll
        for (int nt = 0; nt < 8; nt++)
            #pragma unroll
            for (int e = 0; e < 4; e++) d[nt][e] = 0.f;

        #pragma unroll
        for (int ks = 0; ks < 8; ks++) {
            uint4 af = pk[(s * 8 + ks) * 32 + lane];
            int k0 = ks * 8;
            #pragma unroll
            for (int nt = 0; nt < 8; nt++) {
                int n = nt * 8;
                u32 b0 = s_in[(k0 + q4) * STRK + n + g];
                u32 b1 = s_in[(k0 + q4 + 4) * STRK + n + g];
                mma_tf32(d[nt], af.x, af.y, af.z, af.w, b0, b1);
            }
        }
        #pragma unroll
        for (int nt = 0; nt < 8; nt++) {
            int px = nt * 8 + q4 * 2;
            *(bf162*)&g_h[((size_t)(b * CH6 + m0 + g)) * HWn + pxoff + px] =
                __floats2bfloat162_rn(d[nt][0], d[nt][1]);
            *(bf162*)&g_h[((size_t)(b * CH6 + m0 + g + 8)) * HWn + pxoff + px] =
                __floats2bfloat162_rn(d[nt][2], d[nt][3]);
        }
    }
}

// ---------------------------------------------------------------------------
// K4b: generic FFN spectral conv, in-place on g_h (per-channel delta skip)
// ---------------------------------------------------------------------------
__global__ void __launch_bounds__(256)
k_spectral()
{
    int b  = blockIdx.x >> 10;
    int ch = blockIdx.x & 1023;
    for (int c = threadIdx.x; c < CH6; c += 256) {
        if (g_isdelta[c]) continue;
        bf16* p = g_h + ((size_t)(b * CH6 + c)) * HWn + (size_t)ch * 64;
        float t[64];
        #pragma unroll
        for (int i = 0; i < 64; i++) t[i] = __bfloat162float(p[i]);
        const float* gk = &g_gker[c * 64];
        float o[64];
        for (int i = 0; i < 8; i++)
            for (int j = 0; j < 8; j++) {
                float v = 0.f;
                for (int a = 0; a < 8; a++) {
                    int ri = ((i - a) & 7) * 8;
                    #pragma unroll
                    for (int bb = 0; bb < 8; bb++)
                        v += t[ri + ((j - bb) & 7)] * gk[a * 8 + bb];
                }
                o[i * 8 + j] = v;
            }
        #pragma unroll
        for (int i = 0; i < 64; i++) p[i] = __float2bfloat16(o[i]);
    }
}

// ---------------------------------------------------------------------------
// K2/K5: depthwise 3x3 (bf16 in/out)
// ---------------------------------------------------------------------------
__global__ void __launch_bounds__(256, 4)
k_dw(const float* __restrict__ wt)
{
    __shared__ float s[34][Wimg];
    int plane = blockIdx.y;
    int c = plane % CH6;
    int r0 = blockIdx.x * 32;
    int tid = threadIdx.x;
    const bf16* ip = g_h  + (size_t)plane * HWn;
    bf16*       op = g_h2 + (size_t)plane * HWn;

    #pragma unroll
    for (int it = 0; it < 5; it++) {
        int pid = tid + it * 256;
        if (pid < 1088) {
            int row = pid >> 5;            // 0..33
            int q8  = (pid & 31) * 8;      // 0..248
            int gr = r0 + row - 1;
            if (gr >= 0 && gr < Himg) {
                uint4 v = *(const uint4*)&ip[gr * Wimg + q8];
                float f[8];
                bf8_to_f8(v, f);
                *(float4*)&s[row][q8]     = *(float4*)&f[0];
                *(float4*)&s[row][q8 + 4] = *(float4*)&f[4];
            } else {
                float4 z = make_float4(0.f, 0.f, 0.f, 0.f);
                *(float4*)&s[row][q8]     = z;
                *(float4*)&s[row][q8 + 4] = z;
            }
        }
    }
    float w[9];
    #pragma unroll
    for (int i = 0; i < 9; i++) w[i] = __ldg(&wt[c * 9 + i]);
    __syncthreads();

    int rgrp = tid >> 6;                // 0..3
    int c0 = (tid & 63) * 4;            // 0,4,...,252
    int srow0 = rgrp * 8;

    float p0[4] = {0.f, 0.f, 0.f, 0.f};
    float p1[4] = {0.f, 0.f, 0.f, 0.f};
    #pragma unroll
    for (int rr = 0; rr < 10; rr++) {
        int sr = srow0 + rr;
        float4 m = *(const float4*)&s[sr][c0];
        float mm[6];
        mm[0] = (c0 > 0)          ? s[sr][c0 - 1] : 0.f;
        mm[1] = m.x; mm[2] = m.y; mm[3] = m.z; mm[4] = m.w;
        mm[5] = (c0 + 4 < Wimg)   ? s[sr][c0 + 4] : 0.f;

        float h0[4], h1[4], h2[4];
        #pragma unroll
        for (int j = 0; j < 4; j++) {
            h0[j] = fmaf(mm[j], w[0], fmaf(mm[j + 1], w[1], mm[j + 2] * w[2]));
            h1[j] = fmaf(mm[j], w[3], fmaf(mm[j + 1], w[4], mm[j + 2] * w[5]));
            h2[j] = fmaf(mm[j], w[6], fmaf(mm[j + 1], w[7], mm[j + 2] * w[8]));
        }
        if (rr >= 2) {
            int orow = r0 + srow0 + rr - 2;
            uint2 st;
            *(bf162*)&st.x = __floats2bfloat162_rn(p1[0] + h2[0], p1[1] + h2[1]);
            *(bf162*)&st.y = __floats2bfloat162_rn(p1[2] + h2[2], p1[3] + h2[3]);
            *(uint2*)&op[orow * Wimg + c0] = st;
        }
        #pragma unroll
        for (int j = 0; j < 4; j++) {
            p1[j] = p0[j] + h1[j];
            p0[j] = h0[j];
        }
    }
}

// ---------------------------------------------------------------------------
// K3: attention tail: t = v * circconv8x8(q,k); x1 = x + W2 @ t
// grid 2048, 256 threads; dynamic smem 36.9KB
// q/k stored as bf162 pairs, 16B rows, row-XOR swizzle; conv in HFMA2 (bf16)
//   smem u32 addr(c, r, word) = c*32 + ((r ^ (c&7)) << 2) + word
// ---------------------------------------------------------------------------
__global__ void __launch_bounds__(256, 3)
k_attn(const float* __restrict__ x)
{
    extern __shared__ u32 shu[];
    u32* s_qu  = shu;                   // [128][32] bf162 pairs, swizzled rows
    u32* s_ku  = shu + 4096;            // [128][32]
    u32* s_t_u = shu;                   // [128][STRK] tf32, overlays q (+k head)

    int tid = threadIdx.x;
    int b   = blockIdx.x >> 10;
    int ch  = blockIdx.x & 1023;
    size_t base = (size_t)b * CH6 * HWn + (size_t)ch * 64;

    // stage q,k: raw uint4 copies (no conversion), row-swizzled
    #pragma unroll
    for (int it = 0; it < 4; it++) {
        int i = tid + it * 256;
        int c = i >> 3, r = i & 7;
        int off = c * 32 + ((r ^ (c & 7)) << 2);
        uint4 qv = *(const uint4*)&g_h2[base + (size_t)c * HWn + r * 8];
        uint4 kv = *(const uint4*)&g_h2[base + (size_t)(CH2 + c) * HWn + r * 8];
        *(uint4*)&s_qu[off] = qv;
        *(uint4*)&s_ku[off] = kv;
    }
    __syncthreads();

    // circular conv in bf16 HFMA2: thread = (channel c=tid>>1, half); rows i0..i0+3
    int c  = tid >> 1;
    int i0 = (tid & 1) * 4;
    int sw = (c & 7);
    const u32* qb = s_qu + c * 32;
    const u32* kb = s_ku + c * 32;

    bf162 o2[4][4];
    bf162 zz = __float2bfloat162_rn(0.f);
    #pragma unroll
    for (int di = 0; di < 4; di++)
        #pragma unroll
        for (int p = 0; p < 4; p++) o2[di][p] = zz;

    #pragma unroll 2
    for (int a = 0; a < 8; a++) {
        uint4 kw = *(const uint4*)&kb[(a ^ sw) << 2];
        u32 kwu[4] = {kw.x, kw.y, kw.z, kw.w};
        bf162 kd[8];
        #pragma unroll
        for (int wdx = 0; wdx < 4; wdx++) {
            bf162 kp = *(bf162*)&kwu[wdx];
            kd[2 * wdx]     = __low2bfloat162(kp);
            kd[2 * wdx + 1] = __high2bfloat162(kp);
        }
        #pragma unroll
        for (int di = 0; di < 4; di++) {
            int rr = (i0 + di - a) & 7;
            uint4 qw = *(const uint4*)&qb[(rr ^ sw) << 2];
            u32 q2u[4] = {qw.x, qw.y, qw.z, qw.w};
            u32 qr2u[4];
            #pragma unroll
            for (int p = 0; p < 4; p++)
                qr2u[p] = __byte_perm(q2u[p], q2u[(p + 1) & 3], 0x5432);
            bf162* q2  = (bf162*)q2u;
            bf162* qr2 = (bf162*)qr2u;
            #pragma unroll
            for (int m = 0; m < 4; m++) {
                #pragma unroll
                for (int p = 0; p < 4; p++) {
                    o2[di][p] = __hfma2(q2[(p - m) & 3],      kd[2 * m],     o2[di][p]);
                    o2[di][p] = __hfma2(qr2[(p - m - 1) & 3], kd[2 * m + 1], o2[di][p]);
                }
            }
        }
    }

    // multiply by v (bf162) and convert to tf32 rows
    u32 trow[4][8];
    {
        const bf16* vbase = g_h2 + base + (size_t)(2 * CH2 + c) * HWn;
        #pragma unroll
        for (int di = 0; di < 4; di++) {
            uint4 vv = *(const uint4*)&vbase[(i0 + di) * 8];
            u32 vvu[4] = {vv.x, vv.y, vv.z, vv.w};
            #pragma unroll
            for (int p = 0; p < 4; p++) {
                bf162 prod = __hmul2(o2[di][p], *(bf162*)&vvu[p]);
                float2 f = __bfloat1622float2(prod);
                trow[di][p * 2]     = to_tf32(f.x);
                trow[di][p * 2 + 1] = to_tf32(f.y);
            }
        }
    }
    __syncthreads();     // all conv reads of q/k done; safe to overlay t
    #pragma unroll
    for (int di = 0; di < 4; di++) {
        *(uint4*)&s_t_u[c * STRK + (i0 + di) * 8]     = *(uint4*)&trow[di][0];
        *(uint4*)&s_t_u[c * STRK + (i0 + di) * 8 + 4] = *(uint4*)&trow[di][4];
    }
    __syncthreads();

    // mma: M=64px, N=64oc, K=128
    int warp = tid >> 5, lane = tid & 31;
    int g = lane >> 2, q4 = lane & 3;
    int m0 = (warp & 3) * 16, n0 = (warp >> 2) * 32;
    int ntg0 = (warp >> 2) * 4;

    float d[4][4];
    #pragma unroll
    for (int nt = 0; nt < 4; nt++)
        #pragma unroll
        for (int e = 0; e < 4; e++) d[nt][e] = 0.f;

    #pragma unroll 4
    for (int ks = 0; ks < 16; ks++) {
        int k0 = ks * 8;
        u32 a0 = s_t_u[(k0 + q4) * STRK + m0 + g];
        u32 a1 = s_t_u[(k0 + q4) * STRK + m0 + g + 8];
        u32 a2 = s_t_u[(k0 + q4 + 4) * STRK + m0 + g];
        u32 a3 = s_t_u[(k0 + q4 + 4) * STRK + m0 + g + 8];
        #pragma unroll
        for (int nt = 0; nt < 4; nt++) {
            uint2 bf = g_pkB2[(ks * 8 + ntg0 + nt) * 32 + lane];
            mma_tf32(d[nt], a0, a1, a2, a3, bf.x, bf.y);
        }
    }

    #pragma unroll
    for (int nt = 0; nt < 4; nt++) {
        int oc = n0 + nt * 8 + q4 * 2;
        int px = m0 + g;
        size_t a00 = ((size_t)(b * DIM + oc)) * HWn + (size_t)ch * 64;
        size_t a01 = a00 + HWn;
        g_x1[a00 + px]     = x[a00 + px]     + d[nt][0];
        g_x1[a01 + px]     = x[a01 + px]     + d[nt][1];
        g_x1[a00 + px + 8] = x[a00 + px + 8] + d[nt][2];
        g_x1[a01 + px + 8] = x[a01 + px + 8] + d[nt][3];
    }
}

// ---------------------------------------------------------------------------
// K6: FFN tail: t = gelu(h2a)*h2b; out = x1 + W3 @ t   (tanh.approx gelu)
// ---------------------------------------------------------------------------
__global__ void __launch_bounds__(256, 3)
k_ffn_out(float* __restrict__ dout)
{
    extern __shared__ u32 shu[];
    u32* s_t_u = shu;                   // [192][STRK]

    int tid = threadIdx.x;
    int b   = blockIdx.x >> 10;
    int ch  = blockIdx.x & 1023;
    size_t base = (size_t)b * CH6 * HWn + (size_t)ch * 64;

    #pragma unroll
    for (int it = 0; it < 6; it++) {
        int i = tid + it * 256;
        int c = i >> 3, p8 = (i & 7) * 8;
        uint4 av4 = *(const uint4*)&g_h2[base + (size_t)c * HWn + p8];
        uint4 bv4 = *(const uint4*)&g_h2[base + (size_t)(HID + c) * HWn + p8];
        float af[8], bfv[8];
        bf8_to_f8(av4, af);
        bf8_to_f8(bv4, bfv);
        u32 tv[8];
        #pragma unroll
        for (int j = 0; j < 8; j++) {
            float a = af[j];
            float y = 0.7978845608028654f * (a + 0.044715f * a * a * a);
            float ge = 0.5f * a * (1.f + tanh_ap(y));
            tv[j] = to_tf32(ge * bfv[j]);
        }
        *(uint4*)&s_t_u[c * STRK + p8]     = *(uint4*)&tv[0];
        *(uint4*)&s_t_u[c * STRK + p8 + 4] = *(uint4*)&tv[4];
    }
    __syncthreads();

    int warp = tid >> 5, lane = tid & 31;
    int g = lane >> 2, q4 = lane & 3;
    int m0 = (warp & 3) * 16, n0 = (warp >> 2) * 32;
    int ntg0 = (warp >> 2) * 4;

    float d[4][4];
    #pragma unroll
    for (int nt = 0; nt < 4; nt++)
        #pragma unroll
        for (int e = 0; e < 4; e++) d[nt][e] = 0.f;

    #pragma unroll 4
    for (int ks = 0; ks < 24; ks++) {
        int k0 = ks * 8;
        u32 a0 = s_t_u[(k0 + q4) * STRK + m0 + g];
        u32 a1 = s_t_u[(k0 + q4) * STRK + m0 + g + 8];
        u32 a2 = s_t_u[(k0 + q4 + 4) * STRK + m0 + g];
        u32 a3 = s_t_u[(k0 + q4 + 4) * STRK + m0 + g + 8];
        #pragma unroll
        for (int nt = 0; nt < 4; nt++) {
            uint2 bf = g_pkB3[(ks * 8 + ntg0 + nt) * 32 + lane];
            mma_tf32(d[nt], a0, a1, a2, a3, bf.x, bf.y);
        }
    }

    #pragma unroll
    for (int nt = 0; nt < 4; nt++) {
        int oc = n0 + nt * 8 + q4 * 2;
        int px = m0 + g;
        size_t a00 = ((size_t)(b * DIM + oc)) * HWn + (size_t)ch * 64;
        size_t a01 = a00 + HWn;
        dout[a00 + px]     = g_x1[a00 + px]     + d[nt][0];
        dout[a01 + px]     = g_x1[a01 + px]     + d[nt][1];
        dout[a00 + px + 8] = g_x1[a00 + px + 8] + d[nt][2];
        dout[a01 + px + 8] = g_x1[a01 + px + 8] + d[nt][3];
    }
}

// ---------------------------------------------------------------------------
// launcher
// ---------------------------------------------------------------------------
extern "C" void kernel_launch(void* const* d_in, const int* in_sizes, int n_in,
                              void* d_out, int out_size)
{
    const float* x     = (const float*)d_in[0];
    const float* n1w   = (const float*)d_in[1];
    const float* n1b   = (const float*)d_in[2];
    const float* apin  = (const float*)d_in[3];
    const float* adw   = (const float*)d_in[4];
    const float* apout = (const float*)d_in[5];
    const float* n2w   = (const float*)d_in[6];
    const float* n2b   = (const float*)d_in[7];
    const float* fpin  = (const float*)d_in[8];
    const float* fdw   = (const float*)d_in[9];
    const float* ffft  = (const float*)d_in[10];
    const float* fpout = (const float*)d_in[11];
    float* out         = (float*)d_out;

    (void)in_sizes; (void)n_in; (void)out_size;

    cudaFuncSetAttribute(k_attn,    cudaFuncAttributeMaxDynamicSharedMemorySize, 36864);
    cudaFuncSetAttribute(k_ffn_out, cudaFuncAttributeMaxDynamicSharedMemorySize, 55296);

    // single merged preparation launch
    k_prep_all<<<736, 64>>>(ffft, apin, fpin, apout, fpout);

    // attention branch
    k_ln_pconv<<<2048, 256>>>(x, n1w, n1b, 0);
    k_dw<<<dim3(8, 2 * CH6), 256>>>(adw);
    k_attn<<<2048, 256, 36864>>>(x);

    // FFN branch
    k_ln_pconv<<<2048, 256>>>(x, n2w, n2b, 1);
    k_spectral<<<2048, 256>>>();
    k_dw<<<dim3(8, 2 * CH6), 256>>>(fdw);
    k_ffn_out<<<2048, 256, 55296>>>(out);
}

// round 16
// speedup vs baseline: 1.0806x; 1.0085x over previous
#include <cuda_runtime.h>
#include <cuda_bf16.h>
#include <math.h>

#define HWn   65536
#define Wimg  256
#define Himg  256
#define DIM   64
#define CH6   384
#define CH2   128
#define HID   192
#define EPS   1e-5f
#define STRK  72      // padded k-major stride for mma A-operand staging

typedef unsigned int u32;
typedef __nv_bfloat16  bf16;
typedef __nv_bfloat162 bf162;

// ---------------------------------------------------------------------------
// Scratch (device globals; no runtime allocation)
// ---------------------------------------------------------------------------
__device__ bf16  g_h [(size_t)2 * CH6 * HWn];   // pconv output (bf16 storage)
__device__ bf16  g_h2[(size_t)2 * CH6 * HWn];   // dwconv output (bf16 storage)
__device__ float g_x1[(size_t)2 * DIM * HWn];   // residual carrier (fp32)
__device__ float g_gker[CH6 * 64];
__device__ int   g_isdelta[CH6];

// fragment-packed tf32 weights
__device__ uint4 g_pkA0[24 * 8 * 32];   // attn pin  [384x64] A-frags
__device__ uint4 g_pkA1[24 * 8 * 32];   // ffn  pin  [384x64] A-frags
__device__ uint2 g_pkB2[16 * 8 * 32];   // attn pout [64x128] B-frags
__device__ uint2 g_pkB3[24 * 8 * 32];   // ffn  pout [64x192] B-frags

__device__ __forceinline__ u32 to_tf32(float f) {
    u32 r; asm("cvt.rna.tf32.f32 %0, %1;" : "=r"(r) : "f"(f)); return r;
}
__device__ __forceinline__ void mma_tf32(float d[4], u32 a0, u32 a1, u32 a2, u32 a3,
                                         u32 b0, u32 b1) {
    asm volatile(
        "mma.sync.aligned.m16n8k8.row.col.f32.tf32.tf32.f32 "
        "{%0,%1,%2,%3}, {%4,%5,%6,%7}, {%8,%9}, {%0,%1,%2,%3};"
        : "+f"(d[0]), "+f"(d[1]), "+f"(d[2]), "+f"(d[3])
        : "r"(a0), "r"(a1), "r"(a2), "r"(a3), "r"(b0), "r"(b1));
}
__device__ __forceinline__ void bf8_to_f8(const uint4 v, float* f) {
    float2 t;
    t = __bfloat1622float2(*(const bf162*)&v.x); f[0] = t.x; f[1] = t.y;
    t = __bfloat1622float2(*(const bf162*)&v.y); f[2] = t.x; f[3] = t.y;
    t = __bfloat1622float2(*(const bf162*)&v.z); f[4] = t.x; f[5] = t.y;
    t = __bfloat1622float2(*(const bf162*)&v.w); f[6] = t.x; f[7] = t.y;
}
__device__ __forceinline__ float tanh_ap(float y) {
    float r; asm("tanh.approx.f32 %0, %1;" : "=f"(r) : "f"(y)); return r;
}

// ---------------------------------------------------------------------------
// K0: ONE merged preparation launch (spectral kernels + all weight packing)
// ---------------------------------------------------------------------------
__global__ void k_prep_all(const float* __restrict__ fp,
                           const float* __restrict__ apin,
                           const float* __restrict__ fpin,
                           const float* __restrict__ apout,
                           const float* __restrict__ fpout)
{
    int blk = blockIdx.x;
    int tid = threadIdx.x;

    if (blk < 384) {
        int c = blk, t = tid;
        int x = t >> 3, y = t & 7;
        float s = 0.f;
        #pragma unroll
        for (int kx = 0; kx < 8; kx++) {
            #pragma unroll
            for (int ky = 0; ky < 8; ky++) {
                float Sv = (ky <= 4) ? fp[c * 40 + kx * 5 + ky]
                                     : fp[c * 40 + (((8 - kx) & 7) * 5) + (8 - ky)];
                int m = (kx * x + ky * y) & 7;
                s += Sv * cospif((float)m * 0.25f);
            }
        }
        s *= (1.f / 64.f);
        g_gker[c * 64 + t] = s;
        float target = (t == 0) ? 1.f : 0.f;
        int ok = __syncthreads_and(fabsf(s - target) <= 1e-5f);
        if (t == 0) g_isdelta[c] = ok;
        return;
    }

    int lane = tid & 31;
    int g = lane >> 2, q4 = lane & 3;

    if (blk < 576) {
        int which = (blk >= 480);
        const float* W = which ? fpin : apin;
        int combo = (blk - (which ? 480 : 384)) * 2 + (tid >> 5);
        int s = combo >> 3, ks = combo & 7;
        int m0 = s * 16, k0 = ks * 8;
        uint4 v;
        v.x = to_tf32(W[(m0 + g) * 64 + k0 + q4]);
        v.y = to_tf32(W[(m0 + g + 8) * 64 + k0 + q4]);
        v.z = to_tf32(W[(m0 + g) * 64 + k0 + q4 + 4]);
        v.w = to_tf32(W[(m0 + g + 8) * 64 + k0 + q4 + 4]);
        (which ? g_pkA1 : g_pkA0)[combo * 32 + lane] = v;
        return;
    }

    int which = (blk >= 640);
    const float* W = which ? fpout : apout;
    int IC = which ? HID : CH2;
    int combo = (blk - (which ? 640 : 576)) * 2 + (tid >> 5);
    int ks = combo >> 3, nt = combo & 7;
    int n = nt * 8, k0 = ks * 8;
    uint2 v;
    v.x = to_tf32(W[(n + g) * IC + k0 + q4]);
    v.y = to_tf32(W[(n + g) * IC + k0 + q4 + 4]);
    (which ? g_pkB3 : g_pkB2)[combo * 32 + lane] = v;
}

// ---------------------------------------------------------------------------
// K1/K4: fused LayerNorm + 1x1 conv [384oc x 64ic] via tf32 mma -> bf16 g_h
// ---------------------------------------------------------------------------
__global__ void __launch_bounds__(256, 3)
k_ln_pconv(const float* __restrict__ xin,
           const float* __restrict__ nw,
           const float* __restrict__ nb,
           int which)       // 0: attn (in=xin, pkA0)  1: ffn (in=g_x1, pkA1)
{
    __shared__ u32 s_in[64 * STRK];

    const float* in = which ? g_x1 : xin;
    const uint4* pk = which ? g_pkA1 : g_pkA0;

    int tid = threadIdx.x;
    int b   = blockIdx.x >> 10;
    int ch  = blockIdx.x & 1023;
    size_t pxoff = (size_t)ch * 64;

    int warp = tid >> 5, lane = tid & 31;

    // LayerNorm: 8 warps x 8 rows
    #pragma unroll
    for (int r = 0; r < 8; r++) {
        int ic = warp * 8 + r;
        const float* xr = in + ((size_t)(b * DIM + ic)) * HWn + pxoff;
        float2 v = *(const float2*)&xr[lane * 2];
        float s = v.x + v.y;
        float q = v.x * v.x + v.y * v.y;
        #pragma unroll
        for (int o = 16; o; o >>= 1) {
            s += __shfl_xor_sync(0xffffffffu, s, o);
            q += __shfl_xor_sync(0xffffffffu, q, o);
        }
        float mu  = s * (1.f / 64.f);
        float var = q * (1.f / 64.f) - mu * mu;
        float inv = rsqrtf(var + EPS);
        int j = lane * 2;
        float y0 = (v.x - mu) * inv * nw[j]     + nb[j];
        float y1 = (v.y - mu) * inv * nw[j + 1] + nb[j + 1];
        uint2 pkv = make_uint2(to_tf32(y0), to_tf32(y1));
        *(uint2*)&s_in[ic * STRK + j] = pkv;
    }
    __syncthreads();

    int g  = lane >> 2;
    int q4 = lane & 3;

    for (int s = warp; s < 24; s += 8) {
        int m0 = s * 16;
        float d[8][4];
        #pragma unroll
        for (int nt = 0; nt < 8; nt++)
            #pragma unroll
            for (int e = 0; e < 4; e++) d[nt][e] = 0.f;

        #pragma unroll
        for (int ks = 0; ks < 8; ks++) {
            uint4 af = pk[(s * 8 + ks) * 32 + lane];
            int k0 = ks * 8;
            #pragma unroll
            for (int nt = 0; nt < 8; nt++) {
                int n = nt * 8;
                u32 b0 = s_in[(k0 + q4) * STRK + n + g];
                u32 b1 = s_in[(k0 + q4 + 4) * STRK + n + g];
                mma_tf32(d[nt], af.x, af.y, af.z, af.w, b0, b1);
            }
        }
        #pragma unroll
        for (int nt = 0; nt < 8; nt++) {
            int px = nt * 8 + q4 * 2;
            *(bf162*)&g_h[((size_t)(b * CH6 + m0 + g)) * HWn + pxoff + px] =
                __floats2bfloat162_rn(d[nt][0], d[nt][1]);
            *(bf162*)&g_h[((size_t)(b * CH6 + m0 + g + 8)) * HWn + pxoff + px] =
                __floats2bfloat162_rn(d[nt][2], d[nt][3]);
        }
    }
}

// ---------------------------------------------------------------------------
// K4b: generic FFN spectral conv, in-place on g_h.
// grid 384 blocks (one channel each): all-delta channels exit immediately,
// making this a ~2us no-op for delta inputs while staying fully generic.
// ---------------------------------------------------------------------------
__global__ void __launch_bounds__(256)
k_spectral()
{
    int c = blockIdx.x;
    if (g_isdelta[c]) return;
    const float* gk = &g_gker[c * 64];
    for (int t = threadIdx.x; t < 2048; t += 256) {
        int b  = t >> 10;
        int ch = t & 1023;
        bf16* p = g_h + ((size_t)(b * CH6 + c)) * HWn + (size_t)ch * 64;
        float tt[64];
        #pragma unroll
        for (int i = 0; i < 64; i++) tt[i] = __bfloat162float(p[i]);
        float o[64];
        for (int i = 0; i < 8; i++)
            for (int j = 0; j < 8; j++) {
                float v = 0.f;
                for (int a = 0; a < 8; a++) {
                    int ri = ((i - a) & 7) * 8;
                    #pragma unroll
                    for (int bb = 0; bb < 8; bb++)
                        v += tt[ri + ((j - bb) & 7)] * gk[a * 8 + bb];
                }
                o[i * 8 + j] = v;
            }
        #pragma unroll
        for (int i = 0; i < 64; i++) p[i] = __float2bfloat16(o[i]);
    }
}

// ---------------------------------------------------------------------------
// K2/K5: depthwise 3x3 (bf16 in/out)
// ---------------------------------------------------------------------------
__global__ void __launch_bounds__(256, 4)
k_dw(const float* __restrict__ wt)
{
    __shared__ float s[34][Wimg];
    int plane = blockIdx.y;
    int c = plane % CH6;
    int r0 = blockIdx.x * 32;
    int tid = threadIdx.x;
    const bf16* ip = g_h  + (size_t)plane * HWn;
    bf16*       op = g_h2 + (size_t)plane * HWn;

    #pragma unroll
    for (int it = 0; it < 5; it++) {
        int pid = tid + it * 256;
        if (pid < 1088) {
            int row = pid >> 5;            // 0..33
            int q8  = (pid & 31) * 8;      // 0..248
            int gr = r0 + row - 1;
            if (gr >= 0 && gr < Himg) {
                uint4 v = *(const uint4*)&ip[gr * Wimg + q8];
                float f[8];
                bf8_to_f8(v, f);
                *(float4*)&s[row][q8]     = *(float4*)&f[0];
                *(float4*)&s[row][q8 + 4] = *(float4*)&f[4];
            } else {
                float4 z = make_float4(0.f, 0.f, 0.f, 0.f);
                *(float4*)&s[row][q8]     = z;
                *(float4*)&s[row][q8 + 4] = z;
            }
        }
    }
    float w[9];
    #pragma unroll
    for (int i = 0; i < 9; i++) w[i] = __ldg(&wt[c * 9 + i]);
    __syncthreads();

    int rgrp = tid >> 6;                // 0..3
    int c0 = (tid & 63) * 4;            // 0,4,...,252
    int srow0 = rgrp * 8;

    float p0[4] = {0.f, 0.f, 0.f, 0.f};
    float p1[4] = {0.f, 0.f, 0.f, 0.f};
    #pragma unroll
    for (int rr = 0; rr < 10; rr++) {
        int sr = srow0 + rr;
        float4 m = *(const float4*)&s[sr][c0];
        float mm[6];
        mm[0] = (c0 > 0)          ? s[sr][c0 - 1] : 0.f;
        mm[1] = m.x; mm[2] = m.y; mm[3] = m.z; mm[4] = m.w;
        mm[5] = (c0 + 4 < Wimg)   ? s[sr][c0 + 4] : 0.f;

        float h0[4], h1[4], h2[4];
        #pragma unroll
        for (int j = 0; j < 4; j++) {
            h0[j] = fmaf(mm[j], w[0], fmaf(mm[j + 1], w[1], mm[j + 2] * w[2]));
            h1[j] = fmaf(mm[j], w[3], fmaf(mm[j + 1], w[4], mm[j + 2] * w[5]));
            h2[j] = fmaf(mm[j], w[6], fmaf(mm[j + 1], w[7], mm[j + 2] * w[8]));
        }
        if (rr >= 2) {
            int orow = r0 + srow0 + rr - 2;
            uint2 st;
            *(bf162*)&st.x = __floats2bfloat162_rn(p1[0] + h2[0], p1[1] + h2[1]);
            *(bf162*)&st.y = __floats2bfloat162_rn(p1[2] + h2[2], p1[3] + h2[3]);
            *(uint2*)&op[orow * Wimg + c0] = st;
        }
        #pragma unroll
        for (int j = 0; j < 4; j++) {
            p1[j] = p0[j] + h1[j];
            p0[j] = h0[j];
        }
    }
}

// ---------------------------------------------------------------------------
// K3: attention tail: t = v * circconv8x8(q,k); x1 = x + W2 @ t
// grid 2048, 256 threads; dynamic smem 36.9KB; conv in bf16 HFMA2
// tf32 conversion deferred past the overlay sync (o2 regs only) -> 4 blocks/SM
// ---------------------------------------------------------------------------
__global__ void __launch_bounds__(256, 4)
k_attn(const float* __restrict__ x)
{
    extern __shared__ u32 shu[];
    u32* s_qu  = shu;                   // [128][32] bf162 pairs, swizzled rows
    u32* s_ku  = shu + 4096;            // [128][32]
    u32* s_t_u = shu;                   // [128][STRK] tf32, overlays q (+k head)

    int tid = threadIdx.x;
    int b   = blockIdx.x >> 10;
    int ch  = blockIdx.x & 1023;
    size_t base = (size_t)b * CH6 * HWn + (size_t)ch * 64;

    // stage q,k: raw uint4 copies (no conversion), row-swizzled
    #pragma unroll
    for (int it = 0; it < 4; it++) {
        int i = tid + it * 256;
        int c = i >> 3, r = i & 7;
        int off = c * 32 + ((r ^ (c & 7)) << 2);
        uint4 qv = *(const uint4*)&g_h2[base + (size_t)c * HWn + r * 8];
        uint4 kv = *(const uint4*)&g_h2[base + (size_t)(CH2 + c) * HWn + r * 8];
        *(uint4*)&s_qu[off] = qv;
        *(uint4*)&s_ku[off] = kv;
    }
    __syncthreads();

    // circular conv in bf16 HFMA2: thread = (channel c=tid>>1, half); rows i0..i0+3
    int c  = tid >> 1;
    int i0 = (tid & 1) * 4;
    int sw = (c & 7);
    const u32* qb = s_qu + c * 32;
    const u32* kb = s_ku + c * 32;

    bf162 o2[4][4];
    bf162 zz = __float2bfloat162_rn(0.f);
    #pragma unroll
    for (int di = 0; di < 4; di++)
        #pragma unroll
        for (int p = 0; p < 4; p++) o2[di][p] = zz;

    #pragma unroll 2
    for (int a = 0; a < 8; a++) {
        uint4 kw = *(const uint4*)&kb[(a ^ sw) << 2];
        u32 kwu[4] = {kw.x, kw.y, kw.z, kw.w};
        bf162 kd[8];
        #pragma unroll
        for (int wdx = 0; wdx < 4; wdx++) {
            bf162 kp = *(bf162*)&kwu[wdx];
            kd[2 * wdx]     = __low2bfloat162(kp);
            kd[2 * wdx + 1] = __high2bfloat162(kp);
        }
        #pragma unroll
        for (int di = 0; di < 4; di++) {
            int rr = (i0 + di - a) & 7;
            uint4 qw = *(const uint4*)&qb[(rr ^ sw) << 2];
            u32 q2u[4] = {qw.x, qw.y, qw.z, qw.w};
            u32 qr2u[4];
            #pragma unroll
            for (int p = 0; p < 4; p++)
                qr2u[p] = __byte_perm(q2u[p], q2u[(p + 1) & 3], 0x5432);
            bf162* q2  = (bf162*)q2u;
            bf162* qr2 = (bf162*)qr2u;
            #pragma unroll
            for (int m = 0; m < 4; m++) {
                #pragma unroll
                for (int p = 0; p < 4; p++) {
                    o2[di][p] = __hfma2(q2[(p - m) & 3],      kd[2 * m],     o2[di][p]);
                    o2[di][p] = __hfma2(qr2[(p - m - 1) & 3], kd[2 * m + 1], o2[di][p]);
                }
            }
        }
    }

    // multiply by v (bf162), keep bf16 in o2 (16 regs) across the sync
    {
        const bf16* vbase = g_h2 + base + (size_t)(2 * CH2 + c) * HWn;
        #pragma unroll
        for (int di = 0; di < 4; di++) {
            uint4 vv = *(const uint4*)&vbase[(i0 + di) * 8];
            u32 vvu[4] = {vv.x, vv.y, vv.z, vv.w};
            #pragma unroll
            for (int p = 0; p < 4; p++)
                o2[di][p] = __hmul2(o2[di][p], *(bf162*)&vvu[p]);
        }
    }
    __syncthreads();     // all conv reads of q/k done; safe to overlay t

    // convert to tf32 and store (transient regs only)
    #pragma unroll
    for (int di = 0; di < 4; di++) {
        u32 tr[8];
        #pragma unroll
        for (int p = 0; p < 4; p++) {
            float2 f = __bfloat1622float2(o2[di][p]);
            tr[p * 2]     = to_tf32(f.x);
            tr[p * 2 + 1] = to_tf32(f.y);
        }
        *(uint4*)&s_t_u[c * STRK + (i0 + di) * 8]     = *(uint4*)&tr[0];
        *(uint4*)&s_t_u[c * STRK + (i0 + di) * 8 + 4] = *(uint4*)&tr[4];
    }
    __syncthreads();

    // mma: M=64px, N=64oc, K=128
    int warp = tid >> 5, lane = tid & 31;
    int g = lane >> 2, q4 = lane & 3;
    int m0 = (warp & 3) * 16, n0 = (warp >> 2) * 32;
    int ntg0 = (warp >> 2) * 4;

    float d[4][4];
    #pragma unroll
    for (int nt = 0; nt < 4; nt++)
        #pragma unroll
        for (int e = 0; e < 4; e++) d[nt][e] = 0.f;

    #pragma unroll 4
    for (int ks = 0; ks < 16; ks++) {
        int k0 = ks * 8;
        u32 a0 = s_t_u[(k0 + q4) * STRK + m0 + g];
        u32 a1 = s_t_u[(k0 + q4) * STRK + m0 + g + 8];
        u32 a2 = s_t_u[(k0 + q4 + 4) * STRK + m0 + g];
        u32 a3 = s_t_u[(k0 + q4 + 4) * STRK + m0 + g + 8];
        #pragma unroll
        for (int nt = 0; nt < 4; nt++) {
            uint2 bf = g_pkB2[(ks * 8 + ntg0 + nt) * 32 + lane];
            mma_tf32(d[nt], a0, a1, a2, a3, bf.x, bf.y);
        }
    }

    #pragma unroll
    for (int nt = 0; nt < 4; nt++) {
        int oc = n0 + nt * 8 + q4 * 2;
        int px = m0 + g;
        size_t a00 = ((size_t)(b * DIM + oc)) * HWn + (size_t)ch * 64;
        size_t a01 = a00 + HWn;
        g_x1[a00 + px]     = x[a00 + px]     + d[nt][0];
        g_x1[a01 + px]     = x[a01 + px]     + d[nt][1];
        g_x1[a00 + px + 8] = x[a00 + px + 8] + d[nt][2];
        g_x1[a01 + px + 8] = x[a01 + px + 8] + d[nt][3];
    }
}

// ---------------------------------------------------------------------------
// K6: FFN tail: t = gelu(h2a)*h2b; out = x1 + W3 @ t   (tanh.approx gelu)
// ---------------------------------------------------------------------------
__global__ void __launch_bounds__(256, 3)
k_ffn_out(float* __restrict__ dout)
{
    extern __shared__ u32 shu[];
    u32* s_t_u = shu;                   // [192][STRK]

    int tid = threadIdx.x;
    int b   = blockIdx.x >> 10;
    int ch  = blockIdx.x & 1023;
    size_t base = (size_t)b * CH6 * HWn + (size_t)ch * 64;

    #pragma unroll
    for (int it = 0; it < 6; it++) {
        int i = tid + it * 256;
        int c = i >> 3, p8 = (i & 7) * 8;
        uint4 av4 = *(const uint4*)&g_h2[base + (size_t)c * HWn + p8];
        uint4 bv4 = *(const uint4*)&g_h2[base + (size_t)(HID + c) * HWn + p8];
        float af[8], bfv[8];
        bf8_to_f8(av4, af);
        bf8_to_f8(bv4, bfv);
        u32 tv[8];
        #pragma unroll
        for (int j = 0; j < 8; j++) {
            float a = af[j];
            float y = 0.7978845608028654f * (a + 0.044715f * a * a * a);
            float ge = 0.5f * a * (1.f + tanh_ap(y));
            tv[j] = to_tf32(ge * bfv[j]);
        }
        *(uint4*)&s_t_u[c * STRK + p8]     = *(uint4*)&tv[0];
        *(uint4*)&s_t_u[c * STRK + p8 + 4] = *(uint4*)&tv[4];
    }
    __syncthreads();

    int warp = tid >> 5, lane = tid & 31;
    int g = lane >> 2, q4 = lane & 3;
    int m0 = (warp & 3) * 16, n0 = (warp >> 2) * 32;
    int ntg0 = (warp >> 2) * 4;

    float d[4][4];
    #pragma unroll
    for (int nt = 0; nt < 4; nt++)
        #pragma unroll
        for (int e = 0; e < 4; e++) d[nt][e] = 0.f;

    #pragma unroll 4
    for (int ks = 0; ks < 24; ks++) {
        int k0 = ks * 8;
        u32 a0 = s_t_u[(k0 + q4) * STRK + m0 + g];
        u32 a1 = s_t_u[(k0 + q4) * STRK + m0 + g + 8];
        u32 a2 = s_t_u[(k0 + q4 + 4) * STRK + m0 + g];
        u32 a3 = s_t_u[(k0 + q4 + 4) * STRK + m0 + g + 8];
        #pragma unroll
        for (int nt = 0; nt < 4; nt++) {
            uint2 bf = g_pkB3[(ks * 8 + ntg0 + nt) * 32 + lane];
            mma_tf32(d[nt], a0, a1, a2, a3, bf.x, bf.y);
        }
    }

    #pragma unroll
    for (int nt = 0; nt < 4; nt++) {
        int oc = n0 + nt * 8 + q4 * 2;
        int px = m0 + g;
        size_t a00 = ((size_t)(b * DIM + oc)) * HWn + (size_t)ch * 64;
        size_t a01 = a00 + HWn;
        dout[a00 + px]     = g_x1[a00 + px]     + d[nt][0];
        dout[a01 + px]     = g_x1[a01 + px]     + d[nt][1];
        dout[a00 + px + 8] = g_x1[a00 + px + 8] + d[nt][2];
        dout[a01 + px + 8] = g_x1[a01 + px + 8] + d[nt][3];
    }
}

// ---------------------------------------------------------------------------
// launcher
// ---------------------------------------------------------------------------
extern "C" void kernel_launch(void* const* d_in, const int* in_sizes, int n_in,
                              void* d_out, int out_size)
{
    const float* x     = (const float*)d_in[0];
    const float* n1w   = (const float*)d_in[1];
    const float* n1b   = (const float*)d_in[2];
    const float* apin  = (const float*)d_in[3];
    const float* adw   = (const float*)d_in[4];
    const float* apout = (const float*)d_in[5];
    const float* n2w   = (const float*)d_in[6];
    const float* n2b   = (const float*)d_in[7];
    const float* fpin  = (const float*)d_in[8];
    const float* fdw   = (const float*)d_in[9];
    const float* ffft  = (const float*)d_in[10];
    const float* fpout = (const float*)d_in[11];
    float* out         = (float*)d_out;

    (void)in_sizes; (void)n_in; (void)out_size;

    cudaFuncSetAttribute(k_attn,    cudaFuncAttributeMaxDynamicSharedMemorySize, 36864);
    cudaFuncSetAttribute(k_ffn_out, cudaFuncAttributeMaxDynamicSharedMemorySize, 55296);

    // single merged preparation launch
    k_prep_all<<<736, 64>>>(ffft, apin, fpin, apout, fpout);

    // attention branch
    k_ln_pconv<<<2048, 256>>>(x, n1w, n1b, 0);
    k_dw<<<dim3(8, 2 * CH6), 256>>>(adw);
    k_attn<<<2048, 256, 36864>>>(x);

    // FFN branch
    k_ln_pconv<<<2048, 256>>>(x, n2w, n2b, 1);
    k_spectral<<<384, 256>>>();
    k_dw<<<dim3(8, 2 * CH6), 256>>>(fdw);
    k_ffn_out<<<2048, 256, 55296>>>(out);
}